// round 17
// baseline (speedup 1.0000x reference)
#include <cuda_runtime.h>
#include <math.h>

#define Bb      128
#define Ll      2048
#define NOBS    32
#define NHID    512
#define NSTEPS  (Ll - 1)          // 2047
#define NCTA    128
#define NTHREADS 64               // 2 warps
typedef unsigned long long u64;
typedef unsigned int u32;
#define NBUMPS  ((u32)(NSTEPS - 1))   // 2046 bumps per warp per replay

// SMEM: A interleaved [256 k2][16 q][4 floats] + per-warp X [4 pairs][514] u64
#define SA2_FLOATS (256 * 16 * 4)               // 65536 B
#define SXW_U64    (4 * 514)                    // per-warp X region
#define SMEM_BYTES (SA2_FLOATS * 4 + 2 * SXW_U64 * 8)   // 98432 B

// per-(m-tile, warp, n-tile) producer flags; one 128B line per (mt,w)
__device__ __align__(128) u32 g_flags[8][2][32];

// ---------------------------------------------------------------------------
__device__ __forceinline__ u64 pack2(float a, float b) {
    u64 r;
    asm("mov.b64 %0, {%1, %2};" : "=l"(r) : "f"(a), "f"(b));
    return r;
}
__device__ __forceinline__ void unpack2(u64 v, float& a, float& b) {
    asm("mov.b64 {%0, %1}, %2;" : "=f"(a), "=f"(b) : "l"(v));
}
__device__ __forceinline__ void ffma2(u64& acc, u64 a, u64 x) {
    asm("fma.rn.f32x2 %0, %1, %2, %0;" : "+l"(acc) : "l"(a), "l"(x));
}
__device__ __forceinline__ u64 acq64(const u32* p) {
    u64 v;
    asm volatile("ld.global.acquire.gpu.u64 %0, [%1];" : "=l"(v) : "l"(p));
    return v;
}
__device__ __forceinline__ u32 acq32(const u32* p) {
    u32 v;
    asm volatile("ld.global.acquire.gpu.u32 %0, [%1];" : "=r"(v) : "l"(p));
    return v;
}
// spin until both u32 halves at f2 (8B-aligned) reach bt
__device__ __forceinline__ void wait2(const u32* f2, u32 bt) {
    u64 v = acq64(f2);
    while ((u32)v < bt || (u32)(v >> 32) < bt) v = acq64(f2);
}

// XLA EmitFastTanh (fma path) — verified bit-exact (rel_err 0.0). DO NOT CHANGE.
__device__ __forceinline__ float tanh_xla(float x) {
    const float kClamp = 7.99881172180175781f;
    float xc = fminf(fmaxf(x, -kClamp), kClamp);
    float x2 = __fmul_rn(xc, xc);
    float num = -2.76076847742355e-16f;
    num = fmaf(x2, num, 2.00018790482477e-13f);
    num = fmaf(x2, num, -8.60467152213735e-11f);
    num = fmaf(x2, num, 5.12229709037114e-08f);
    num = fmaf(x2, num, 1.48572235717979e-05f);
    num = fmaf(x2, num, 6.37261928875436e-04f);
    num = fmaf(x2, num, 4.89352455891786e-03f);
    num = __fmul_rn(xc, num);
    float den = 1.19825839466702e-06f;
    den = fmaf(x2, den, 1.18534705686654e-04f);
    den = fmaf(x2, den, 2.26843463243900e-03f);
    den = fmaf(x2, den, 4.89352518554385e-03f);
    float r = __fdiv_rn(num, den);
    return (fabsf(x) < 0.0004f) ? x : r;
}

// ---------------------------------------------------------------------------
// Persistent HCNN scan, order-exact fp32, warp-autonomous, 2 warps x (2x2).
// 128 CTAs = 16 n-tiles (32 cols) x 8 m-tiles (16 batches = 8 pairs).
// Warp w (of 2) owns pairs {4w..4w+3}: stages them into its SMEM X region,
// computes a 2-pair x 2-col register tile per lane (ph = l>>4 selects pairs
// 4w+2ph, 4w+2ph+1; q = l&15 selects cols), publishes g_flags[mt][w][nt].
// Crossbar request bytes drop 1MB -> 768KB per SM per step vs R13.
// ffma2 chain values + order identical to the bit-exact R13 kernel.
// ---------------------------------------------------------------------------
__global__ void __launch_bounds__(NTHREADS, 1) ptf_persistent(
    const float* __restrict__ data,   // [B, L, NOBS]
    const float* __restrict__ Amat,   // [NHID, NHID]
    const float* __restrict__ h0,     // [NHID]
    float* __restrict__ exps,
    float* __restrict__ states,       // doubles as the recurrent state
    float* __restrict__ deltas,
    float* __restrict__ partials)
{
    extern __shared__ char smem_raw[];
    float* sA2   = (float*)smem_raw;                      // [256][16][4]
    u64*   sxall = (u64*)(smem_raw + SA2_FLOATS * 4);     // [2 warps][4][514]

    const int tid = threadIdx.x;
    const int w   = tid >> 5;              // warp 0/1
    const int l   = tid & 31;
    const int nt  = blockIdx.x & 15;
    const int mt  = blockIdx.x >> 4;
    const int n0  = nt * 32;
    const int m0  = mt * 16;

    const u32* flagrow = &g_flags[mt][w][0];
    u32* myflag = &g_flags[mt][w][nt];
    u32 base = acq32(myflag);
    base -= base % NBUMPS;                 // monotonic across graph replays

    // ---- one-time: A -> sA2[k2][q][4] = {a_n[2k2],a_n[2k2+1],a_n1[2k2],a_n1[2k2+1]}
    for (int i = tid; i < 256 * 16; i += NTHREADS) {
        const int k2 = i >> 4;
        const int qq = i & 15;
        const int n  = n0 + 2 * qq;
        float2 a0 = *(const float2*)&Amat[(size_t)n * NHID + 2 * k2];
        float2 a1 = *(const float2*)&Amat[(size_t)(n + 1) * NHID + 2 * k2];
        *(float4*)&sA2[(size_t)i * 4] = make_float4(a0.x, a0.y, a1.x, a1.y);
    }
    __syncthreads();                       // only CTA-wide sync in the kernel

    // compute-lane identifiers
    const int ph = l >> 4;                 // pair-group half 0/1
    const int q  = l & 15;                 // col-pair index
    const int P0 = 4 * w + 2 * ph;         // lane's pairs P0, P0+1
    const int bA0 = m0 + P0, bB0 = bA0 + 8;
    const int bA1 = bA0 + 1, bB1 = bA1 + 8;
    const int nA = n0 + 2 * q;             // compute cols nA, nA+1
    u64* xw = sxall + (size_t)w * SXW_U64; // warp's 4 X rows
    const u64* x0r = xw + (size_t)(2 * ph) * 514;
    const u64* x1r = x0r + 514;

    // staging units: u = l and l+32; unit -> (pi = u>>4, j = u&15)
    const int u0_pi = l >> 4,        u0_j = l & 15;
    const int u1_pi = (l + 32) >> 4, u1_j = l & 15;   // pi+2, same j

    for (int t = 0; t < NSTEPS; t++) {
        const u32 bt = base + (u32)t;

        // ---------- stage chunk 0 (k 0..63; includes injection/outputs) ------
        if (t > 0) wait2(flagrow, bt);     // producers nt=0,1
        #pragma unroll
        for (int uu = 0; uu < 2; uu++) {
            const int pi = uu ? u1_pi : u0_pi;   // 0..3
            const int j  = uu ? u1_j  : u0_j;
            const int k  = 4 * j;                // 0..60 (chunk 0)
            const int sb = m0 + 4 * w + pi;      // batch row A of this pair
            const int tb = sb + 8;               // batch row B
            float4 fa, fb;
            if (t == 0) {
                fa = *(const float4*)(h0 + k);
                fb = fa;
                if (nt == 0) {             // states[:,0,:] = s0 (pre-inject)
                    *(float4*)&states[(size_t)sb * Ll * NHID + k] = fa;
                    *(float4*)&states[(size_t)tb * Ll * NHID + k] = fb;
                }
            } else {
                fa = *(const float4*)&states[((size_t)sb * Ll + t) * NHID + k];
                fb = *(const float4*)&states[((size_t)tb * Ll + t) * NHID + k];
            }
            if (j < 8) {                   // k < 32: teacher forcing s + (y-s)
                float4 yA = *(const float4*)&data[((size_t)sb * Ll + t) * NOBS + k];
                float4 yB = *(const float4*)&data[((size_t)tb * Ll + t) * NOBS + k];
                float4 dA, dB;
                dA.x = __fsub_rn(yA.x, fa.x); dA.y = __fsub_rn(yA.y, fa.y);
                dA.z = __fsub_rn(yA.z, fa.z); dA.w = __fsub_rn(yA.w, fa.w);
                dB.x = __fsub_rn(yB.x, fb.x); dB.y = __fsub_rn(yB.y, fb.y);
                dB.z = __fsub_rn(yB.z, fb.z); dB.w = __fsub_rn(yB.w, fb.w);
                if (nt == 0) {
                    size_t oA = ((size_t)sb * Ll + t) * NOBS + k;
                    size_t oB = ((size_t)tb * Ll + t) * NOBS + k;
                    *(float4*)&exps[oA] = fa;  *(float4*)&exps[oB] = fb;
                    *(float4*)&deltas[oA]   = dA; *(float4*)&deltas[oB]   = dB;
                    *(float4*)&partials[oA] = dA; *(float4*)&partials[oB] = dB;
                }
                fa.x = __fadd_rn(fa.x, dA.x); fa.y = __fadd_rn(fa.y, dA.y);
                fa.z = __fadd_rn(fa.z, dA.z); fa.w = __fadd_rn(fa.w, dA.w);
                fb.x = __fadd_rn(fb.x, dB.x); fb.y = __fadd_rn(fb.y, dB.y);
                fb.z = __fadd_rn(fb.z, dB.z); fb.w = __fadd_rn(fb.w, dB.w);
            }
            u64* d = xw + (size_t)pi * 514 + k;
            ulonglong2 lo, hi;
            lo.x = pack2(fa.x, fb.x); lo.y = pack2(fa.y, fb.y);
            hi.x = pack2(fa.z, fb.z); hi.y = pack2(fa.w, fb.w);
            *(ulonglong2*)(d)     = lo;
            *(ulonglong2*)(d + 2) = hi;
        }
        __syncwarp();

        // ---------- chunked compute, prefetch next chunk under FMA -----------
        u64 acc00 = 0, acc01 = 0, acc10 = 0, acc11 = 0;
        #pragma unroll 1
        for (int c = 0; c < 8; c++) {
            float4 g0a, g0b, g1a, g1b;
            const bool more = (c < 7);
            if (more) {                    // poll + LDG chunk c+1 (hidden)
                if (t > 0) wait2(flagrow + 2 * (c + 1), bt);
                {   // unit 0
                    const int sb = m0 + 4 * w + u0_pi, tb = sb + 8;
                    const int kn = 64 * (c + 1) + 4 * u0_j;
                    if (t == 0) {
                        g0a = *(const float4*)(h0 + kn); g0b = g0a;
                        if (nt == 0) {
                            *(float4*)&states[(size_t)sb * Ll * NHID + kn] = g0a;
                            *(float4*)&states[(size_t)tb * Ll * NHID + kn] = g0b;
                        }
                    } else {
                        g0a = *(const float4*)&states[((size_t)sb * Ll + t) * NHID + kn];
                        g0b = *(const float4*)&states[((size_t)tb * Ll + t) * NHID + kn];
                    }
                }
                {   // unit 1
                    const int sb = m0 + 4 * w + u1_pi, tb = sb + 8;
                    const int kn = 64 * (c + 1) + 4 * u1_j;
                    if (t == 0) {
                        g1a = *(const float4*)(h0 + kn); g1b = g1a;
                        if (nt == 0) {
                            *(float4*)&states[(size_t)sb * Ll * NHID + kn] = g1a;
                            *(float4*)&states[(size_t)tb * Ll * NHID + kn] = g1b;
                        }
                    } else {
                        g1a = *(const float4*)&states[((size_t)sb * Ll + t) * NHID + kn];
                        g1b = *(const float4*)&states[((size_t)tb * Ll + t) * NHID + kn];
                    }
                }
            }

            // compute chunk c: k2 in [32c, 32c+32), ascending (bit-exact)
            const u64* xc0 = x0r + 64 * c;
            const u64* xc1 = x1r + 64 * c;
            const float* ac = sA2 + ((size_t)(32 * c * 16) + q) * 4;
            #pragma unroll
            for (int j = 0; j < 32; j++) {
                ulonglong2 X0 = *(const ulonglong2*)(xc0 + 2 * j);
                ulonglong2 X1 = *(const ulonglong2*)(xc1 + 2 * j);
                float4 Aq = *(const float4*)(ac + (size_t)j * 64);
                u64 ax = pack2(Aq.x, Aq.x), az = pack2(Aq.z, Aq.z);
                u64 ay = pack2(Aq.y, Aq.y), aw = pack2(Aq.w, Aq.w);
                ffma2(acc00, ax, X0.x);    // P0, col nA,   k
                ffma2(acc01, az, X0.x);    // P0, col nA+1, k
                ffma2(acc10, ax, X1.x);    // P1, col nA,   k
                ffma2(acc11, az, X1.x);    // P1, col nA+1, k
                ffma2(acc00, ay, X0.y);    // k+1
                ffma2(acc01, aw, X0.y);
                ffma2(acc10, ay, X1.y);
                ffma2(acc11, aw, X1.y);
            }

            if (more) {                    // stage chunk c+1 (no injection: k>=64)
                u64* d0 = xw + (size_t)u0_pi * 514 + 64 * (c + 1) + 4 * u0_j;
                u64* d1 = xw + (size_t)u1_pi * 514 + 64 * (c + 1) + 4 * u1_j;
                ulonglong2 lo, hi;
                lo.x = pack2(g0a.x, g0b.x); lo.y = pack2(g0a.y, g0b.y);
                hi.x = pack2(g0a.z, g0b.z); hi.y = pack2(g0a.w, g0b.w);
                *(ulonglong2*)(d0)     = lo;
                *(ulonglong2*)(d0 + 2) = hi;
                lo.x = pack2(g1a.x, g1b.x); lo.y = pack2(g1a.y, g1b.y);
                hi.x = pack2(g1a.z, g1b.z); hi.y = pack2(g1a.w, g1b.w);
                *(ulonglong2*)(d1)     = lo;
                *(ulonglong2*)(d1 + 2) = hi;
                __syncwarp();
            }
        }

        // ---------- tanh + writes (4 chains = 8 outputs) ---------------------
        float zA0n0, zB0n0, zA0n1, zB0n1, zA1n0, zB1n0, zA1n1, zB1n1;
        unpack2(acc00, zA0n0, zB0n0);
        unpack2(acc01, zA0n1, zB0n1);
        unpack2(acc10, zA1n0, zB1n0);
        unpack2(acc11, zA1n1, zB1n1);
        const float hA0n0 = tanh_xla(zA0n0), hA0n1 = tanh_xla(zA0n1);
        const float hB0n0 = tanh_xla(zB0n0), hB0n1 = tanh_xla(zB0n1);
        const float hA1n0 = tanh_xla(zA1n0), hA1n1 = tanh_xla(zA1n1);
        const float hB1n0 = tanh_xla(zB1n0), hB1n1 = tanh_xla(zB1n1);

        float* so = states + ((size_t)t + 1) * NHID + nA;
        *(float2*)(so + (size_t)bA0 * Ll * NHID) = make_float2(hA0n0, hA0n1);
        *(float2*)(so + (size_t)bB0 * Ll * NHID) = make_float2(hB0n0, hB0n1);
        *(float2*)(so + (size_t)bA1 * Ll * NHID) = make_float2(hA1n0, hA1n1);
        *(float2*)(so + (size_t)bB1 * Ll * NHID) = make_float2(hB1n0, hB1n1);

        if (t == NSTEPS - 1 && nt == 0) {  // nA, nA+1 < 32 here
            const int   bs[4] = {bA0, bB0, bA1, bB1};
            const float hx[4] = {hA0n0, hB0n0, hA1n0, hB1n0};
            const float hy[4] = {hA0n1, hB0n1, hA1n1, hB1n1};
            #pragma unroll
            for (int i = 0; i < 4; i++) {
                size_t o  = ((size_t)bs[i] * Ll + (Ll - 1)) * NOBS + nA;
                size_t dI = ((size_t)bs[i] * Ll + (Ll - 2)) * NOBS + nA;
                exps[o]     = hx[i];
                exps[o + 1] = hy[i];
                float dx = __fsub_rn(data[dI],     hx[i]);
                float dy = __fsub_rn(data[dI + 1], hy[i]);
                deltas[o]       = dx; deltas[o + 1]   = dy;
                partials[o]     = dx; partials[o + 1] = dy;
            }
        }

        // ---------- publish this warp's progress ----------------------------
        if (t < NSTEPS - 1) {
            __syncwarp();                  // order all lanes' STGs (warp fence)
            if (l == 0)
                asm volatile("red.global.release.gpu.add.u32 [%0], %1;"
                             :: "l"(myflag), "r"(1u) : "memory");
        }
    }
}

// ---------------------------------------------------------------------------
extern "C" void kernel_launch(void* const* d_in, const int* in_sizes, int n_in,
                              void* d_out, int out_size) {
    const float* data = (const float*)d_in[0];  // [128,2048,32]
    const float* A    = (const float*)d_in[1];  // [512,512]
    const float* h0   = (const float*)d_in[2];  // [1,512]
    // d_in[3] = prob (0) -> dropout identity

    float* out      = (float*)d_out;
    float* exps     = out;
    float* states   = exps   + (size_t)Bb * Ll * NOBS;
    float* deltas   = states + (size_t)Bb * Ll * NHID;
    float* partials = deltas + (size_t)Bb * Ll * NOBS;

    cudaFuncSetAttribute(ptf_persistent,
                         cudaFuncAttributeMaxDynamicSharedMemorySize, SMEM_BYTES);
    ptf_persistent<<<NCTA, NTHREADS, SMEM_BYTES>>>(data, A, h0,
                                                   exps, states, deltas, partials);
}